// round 10
// baseline (speedup 1.0000x reference)
#include <cuda_runtime.h>
#include <cuda_bf16.h>
#include <cstdint>

#define HDIM 128
#define MAXN 100000
#define MAXE 1600000
#define NB_MAX 128          // max scan blocks: ceil(100000/1024) = 98

// Scratch (device globals; no allocation allowed).
__device__ float g_agg[(size_t)MAXN * HDIM];
__device__ float g_z  [(size_t)MAXN * HDIM];
__device__ float g_h0 [(size_t)MAXN * HDIM];
__device__ float g_h1 [(size_t)MAXN * HDIM];
__device__ int   g_offs[MAXN + 1];
__device__ int   g_cursor[MAXN];
__device__ int   g_ssrc[MAXE];
__device__ int   g_bsum[NB_MAX + 1];
__device__ float g_wt[6][HDIM * HDIM];   // pre-rounded tf32 weights

// GEMM dynamic smem (floats): As0[128*36] Ws0[32*136] As1 Ws1
#define AS_PITCH 36
#define WS_PITCH 136
#define AS_ELEMS (128 * AS_PITCH)
#define WS_ELEMS (32 * WS_PITCH)
#define GEMM_SMEM_BYTES ((AS_ELEMS + WS_ELEMS) * 2 * 4)

// ---------------------------------------------------------------------------
// Helpers
// ---------------------------------------------------------------------------
__device__ __forceinline__ void atomic_add_f4(float4* addr, float4 v) {
#if __CUDA_ARCH__ >= 900
    atomicAdd(addr, v);
#else
    float* f = (float*)addr;
    atomicAdd(f + 0, v.x); atomicAdd(f + 1, v.y);
    atomicAdd(f + 2, v.z); atomicAdd(f + 3, v.w);
#endif
}

__device__ __forceinline__ uint32_t to_tf32(float x) {
    uint32_t r;
    asm("cvt.rna.tf32.f32 %0, %1;" : "=r"(r) : "f"(x));
    return r;
}
__device__ __forceinline__ float round_tf32(float x) {
    return __uint_as_float(to_tf32(x));
}

__device__ __forceinline__ void mma_tf32(float d[4],
                                         uint32_t a0, uint32_t a1, uint32_t a2, uint32_t a3,
                                         uint32_t b0, uint32_t b1) {
    asm volatile(
        "mma.sync.aligned.m16n8k8.row.col.f32.tf32.tf32.f32 "
        "{%0,%1,%2,%3}, {%4,%5,%6,%7}, {%8,%9}, {%0,%1,%2,%3};\n"
        : "+f"(d[0]), "+f"(d[1]), "+f"(d[2]), "+f"(d[3])
        : "r"(a0), "r"(a1), "r"(a2), "r"(a3), "r"(b0), "r"(b1));
}

__device__ __forceinline__ uint32_t smem_u32(const void* p) {
    return (uint32_t)__cvta_generic_to_shared(p);
}
__device__ __forceinline__ void cp_async16(uint32_t saddr, const void* gptr) {
    asm volatile("cp.async.cg.shared.global [%0], [%1], 16;\n" :: "r"(saddr), "l"(gptr));
}
__device__ __forceinline__ void cp_commit() {
    asm volatile("cp.async.commit_group;\n");
}
template <int N>
__device__ __forceinline__ void cp_wait() {
    asm volatile("cp.async.wait_group %0;\n" :: "n"(N));
}

// ---------------------------------------------------------------------------
// Fused weight pre-round: all 6 weight matrices in one launch.
// dst layout: g_wt[i] = tf32_round(Wsrc[i])
// ---------------------------------------------------------------------------
__global__ void round_w6_kernel(float* __restrict__ dst,
                                const float* __restrict__ w0, const float* __restrict__ w1,
                                const float* __restrict__ w2, const float* __restrict__ w3,
                                const float* __restrict__ w4, const float* __restrict__ w5) {
    const float* srcs[6] = {w0, w1, w2, w3, w4, w5};
    int i = blockIdx.x * blockDim.x + threadIdx.x;
    const int n = HDIM * HDIM;
    if (i < 6 * n) {
        int m = i / n;
        int j = i - m * n;
        dst[(size_t)m * n + j] = round_tf32(srcs[m][j]);
    }
}

// ---------------------------------------------------------------------------
// CSR build
// ---------------------------------------------------------------------------
__global__ void zero_int_kernel(int* __restrict__ p, int n) {
    int i = blockIdx.x * blockDim.x + threadIdx.x;
    if (i < n) p[i] = 0;
}

__global__ void hist_kernel(const int* __restrict__ dst, int* __restrict__ count, int E) {
    int e = blockIdx.x * blockDim.x + threadIdx.x;
    if (e < E) atomicAdd(&count[__ldg(&dst[e])], 1);
}

__global__ __launch_bounds__(1024) void scan1_kernel(const int* __restrict__ cnt,
                                                     int* __restrict__ offs,
                                                     int* __restrict__ bsum, int N) {
    __shared__ int sh[1024];
    int t = threadIdx.x;
    int i = blockIdx.x * 1024 + t;
    int v = (i < N) ? cnt[i] : 0;
    sh[t] = v;
    __syncthreads();
    for (int d = 1; d < 1024; d <<= 1) {
        int x = (t >= d) ? sh[t - d] : 0;
        __syncthreads();
        if (t >= d) sh[t] += x;
        __syncthreads();
    }
    if (i < N) offs[i] = sh[t] - v;
    if (t == 1023) bsum[blockIdx.x] = sh[1023];
}

__global__ __launch_bounds__(NB_MAX) void scan2_kernel(int* __restrict__ bsum, int nb) {
    __shared__ int sh[NB_MAX];
    int t = threadIdx.x;
    int v = (t < nb) ? bsum[t] : 0;
    sh[t] = v;
    __syncthreads();
    for (int d = 1; d < NB_MAX; d <<= 1) {
        int x = (t >= d) ? sh[t - d] : 0;
        __syncthreads();
        if (t >= d) sh[t] += x;
        __syncthreads();
    }
    if (t < nb) bsum[t] = sh[t] - v;
    if (t == 0) bsum[nb] = sh[nb - 1];
}

__global__ __launch_bounds__(1024) void scan3_kernel(int* __restrict__ offs,
                                                     int* __restrict__ cursor,
                                                     const int* __restrict__ bsum,
                                                     int N, int nb) {
    int i = blockIdx.x * 1024 + threadIdx.x;
    if (i < N) {
        int v = offs[i] + bsum[blockIdx.x];
        offs[i] = v;
        cursor[i] = v;
    }
    if (i == 0) offs[N] = bsum[nb];
}

__global__ void permute_kernel(const int* __restrict__ src,
                               const int* __restrict__ dst,
                               int* __restrict__ cursor,
                               int* __restrict__ ssrc, int E) {
    int e = blockIdx.x * blockDim.x + threadIdx.x;
    if (e >= E) return;
    int d = __ldg(&dst[e]);
    int pos = atomicAdd(&cursor[d], 1);
    ssrc[pos] = __ldg(&src[e]);
}

// ---------------------------------------------------------------------------
// Gather: agg[n,:] = tf32_round( h[n,:] + sum_{e: dst==n} h[src[e],:] )
// 4-way unrolled: 4 independent accumulators + prefetched indices -> MLP~4.
// ---------------------------------------------------------------------------
__global__ __launch_bounds__(256) void gather_kernel(const float* __restrict__ h,
                                                     const int* __restrict__ ssrc,
                                                     const int* __restrict__ offs,
                                                     float* __restrict__ agg,
                                                     int N) {
    int node = (int)(((size_t)blockIdx.x * blockDim.x + threadIdx.x) >> 5);
    int lane = threadIdx.x & 31;
    if (node >= N) return;
    const float4* hb = (const float4*)h;
    int beg = __ldg(&offs[node]);
    int end = __ldg(&offs[node + 1]);

    float4 v0 = __ldg(hb + (size_t)node * 32 + lane);
    float4 v1 = make_float4(0.f, 0.f, 0.f, 0.f);
    float4 v2 = make_float4(0.f, 0.f, 0.f, 0.f);
    float4 v3 = make_float4(0.f, 0.f, 0.f, 0.f);
    int i = beg;
    for (; i + 3 < end; i += 4) {
        int s0 = __ldg(&ssrc[i]);
        int s1 = __ldg(&ssrc[i + 1]);
        int s2 = __ldg(&ssrc[i + 2]);
        int s3 = __ldg(&ssrc[i + 3]);
        float4 a = __ldg(hb + (size_t)s0 * 32 + lane);
        float4 b = __ldg(hb + (size_t)s1 * 32 + lane);
        float4 cc = __ldg(hb + (size_t)s2 * 32 + lane);
        float4 d = __ldg(hb + (size_t)s3 * 32 + lane);
        v0.x += a.x;  v0.y += a.y;  v0.z += a.z;  v0.w += a.w;
        v1.x += b.x;  v1.y += b.y;  v1.z += b.z;  v1.w += b.w;
        v2.x += cc.x; v2.y += cc.y; v2.z += cc.z; v2.w += cc.w;
        v3.x += d.x;  v3.y += d.y;  v3.z += d.z;  v3.w += d.w;
    }
    for (; i < end; i++) {
        int s0 = __ldg(&ssrc[i]);
        float4 a = __ldg(hb + (size_t)s0 * 32 + lane);
        v0.x += a.x; v0.y += a.y; v0.z += a.z; v0.w += a.w;
    }
    v0.x = round_tf32((v0.x + v1.x) + (v2.x + v3.x));
    v0.y = round_tf32((v0.y + v1.y) + (v2.y + v3.y));
    v0.z = round_tf32((v0.z + v1.z) + (v2.z + v3.z));
    v0.w = round_tf32((v0.w + v1.w) + (v2.w + v3.w));
    ((float4*)agg)[(size_t)node * 32 + lane] = v0;
}

// ---------------------------------------------------------------------------
// Tensor-core GEMM, cp.async double-buffered; inputs pre-rounded tf32,
// zero cvt in the inner loop. ROUND_OUT rounds the stored output (for z).
// ---------------------------------------------------------------------------
__device__ __forceinline__ void gemm_load_stage(
    const float* __restrict__ A, const float* __restrict__ W,
    float* As, float* Ws, int rowBase, int kc, int M, int tid) {
#pragma unroll
    for (int i = tid; i < 1024; i += 256) {
        int r  = i >> 3;
        int c4 = (i & 7) * 4;
        int gr = rowBase + r;
        float* dst = &As[r * AS_PITCH + c4];
        if (gr < M) {
            cp_async16(smem_u32(dst), &A[(size_t)gr * HDIM + kc + c4]);
        } else {
            *(float4*)dst = make_float4(0.f, 0.f, 0.f, 0.f);
        }
    }
#pragma unroll
    for (int i = tid; i < 1024; i += 256) {
        int r  = i >> 5;
        int c4 = (i & 31) * 4;
        cp_async16(smem_u32(&Ws[r * WS_PITCH + c4]), &W[(size_t)(kc + r) * HDIM + c4]);
    }
}

template <bool ROUND_OUT>
__global__ __launch_bounds__(256) void gemm_tc_kernel(
    const float* __restrict__ A,
    const float* __restrict__ W,
    const float* __restrict__ bias,
    float* __restrict__ C,
    int M) {
    extern __shared__ float smem[];
    float* Asb[2] = {smem, smem + AS_ELEMS + WS_ELEMS};
    float* Wsb[2] = {smem + AS_ELEMS, smem + 2 * AS_ELEMS + WS_ELEMS};

    const int tid  = threadIdx.x;
    const int lane = tid & 31;
    const int wid  = tid >> 5;
    const int warp_m = (wid & 3) * 32;
    const int warp_n = (wid >> 2) * 64;
    const int g = lane >> 2;
    const int c = lane & 3;
    const int rowBase = blockIdx.x * 128;

    float acc[2][8][4];
#pragma unroll
    for (int mt = 0; mt < 2; mt++)
#pragma unroll
        for (int nt = 0; nt < 8; nt++)
#pragma unroll
            for (int j = 0; j < 4; j++) acc[mt][nt][j] = 0.f;

    gemm_load_stage(A, W, Asb[0], Wsb[0], rowBase, 0, M, tid);
    cp_commit();

#pragma unroll
    for (int ci = 0; ci < 4; ci++) {
        if (ci < 3) {
            gemm_load_stage(A, W, Asb[(ci + 1) & 1], Wsb[(ci + 1) & 1],
                            rowBase, (ci + 1) * 32, M, tid);
            cp_commit();
            cp_wait<1>();
        } else {
            cp_wait<0>();
        }
        __syncthreads();

        const uint32_t* As = (const uint32_t*)Asb[ci & 1];
        const uint32_t* Ws = (const uint32_t*)Wsb[ci & 1];
#pragma unroll
        for (int ks = 0; ks < 4; ks++) {
            const int k0 = ks * 8;
            uint32_t a[2][4];
#pragma unroll
            for (int mt = 0; mt < 2; mt++) {
                int rb = warp_m + mt * 16;
                a[mt][0] = As[(rb + g    ) * AS_PITCH + k0 + c    ];
                a[mt][1] = As[(rb + 8 + g) * AS_PITCH + k0 + c    ];
                a[mt][2] = As[(rb + g    ) * AS_PITCH + k0 + c + 4];
                a[mt][3] = As[(rb + 8 + g) * AS_PITCH + k0 + c + 4];
            }
#pragma unroll
            for (int nt = 0; nt < 8; nt++) {
                int n = warp_n + nt * 8 + g;
                uint32_t b0 = Ws[(k0 + c    ) * WS_PITCH + n];
                uint32_t b1 = Ws[(k0 + 4 + c) * WS_PITCH + n];
#pragma unroll
                for (int mt = 0; mt < 2; mt++)
                    mma_tf32(acc[mt][nt], a[mt][0], a[mt][1], a[mt][2], a[mt][3], b0, b1);
            }
        }
        __syncthreads();
    }

#pragma unroll
    for (int nt = 0; nt < 8; nt++) {
        int col = warp_n + nt * 8 + 2 * c;
        float2 bb = *(const float2*)&bias[col];
#pragma unroll
        for (int mt = 0; mt < 2; mt++) {
            int row0 = rowBase + warp_m + mt * 16 + g;
            int row1 = row0 + 8;
            if (row0 < M) {
                float2 o;
                o.x = fmaxf(acc[mt][nt][0] + bb.x, 0.f);
                o.y = fmaxf(acc[mt][nt][1] + bb.y, 0.f);
                if (ROUND_OUT) { o.x = round_tf32(o.x); o.y = round_tf32(o.y); }
                *(float2*)&C[(size_t)row0 * HDIM + col] = o;
            }
            if (row1 < M) {
                float2 o;
                o.x = fmaxf(acc[mt][nt][2] + bb.x, 0.f);
                o.y = fmaxf(acc[mt][nt][3] + bb.y, 0.f);
                if (ROUND_OUT) { o.x = round_tf32(o.x); o.y = round_tf32(o.y); }
                *(float2*)&C[(size_t)row1 * HDIM + col] = o;
            }
        }
    }
}

// ---------------------------------------------------------------------------
// Final zero + pool
// ---------------------------------------------------------------------------
__global__ void zero_kernel(float4* __restrict__ p, size_t n4) {
    size_t i = (size_t)blockIdx.x * blockDim.x + threadIdx.x;
    if (i < n4) p[i] = make_float4(0.f, 0.f, 0.f, 0.f);
}

__global__ void pool_kernel(const float* __restrict__ h,
                            const int* __restrict__ batch,
                            float* __restrict__ out,
                            int M) {
    int warp = (int)(((size_t)blockIdx.x * blockDim.x + threadIdx.x) >> 5);
    int lane = threadIdx.x & 31;
    if (warp >= M) return;
    int g = __ldg(&batch[warp]);
    float4 v = __ldg(((const float4*)(h + (size_t)warp * HDIM)) + lane);
    atomic_add_f4(((float4*)(out + (size_t)g * HDIM)) + lane, v);
}

// ---------------------------------------------------------------------------
// Launch
// ---------------------------------------------------------------------------
extern "C" void kernel_launch(void* const* d_in, const int* in_sizes, int n_in,
                              void* d_out, int out_size) {
    const float* x     = (const float*)d_in[0];
    const int*   ei    = (const int*)d_in[1];
    const int*   batch = (const int*)d_in[2];
    const float* Wsrc[6] = {(const float*)d_in[3], (const float*)d_in[5],
                            (const float*)d_in[7], (const float*)d_in[9],
                            (const float*)d_in[11], (const float*)d_in[13]};
    const float* b1[3] = {(const float*)d_in[4], (const float*)d_in[8],  (const float*)d_in[12]};
    const float* b2[3] = {(const float*)d_in[6], (const float*)d_in[10], (const float*)d_in[14]};

    const int Nn = in_sizes[0] / HDIM;
    const int Ee = in_sizes[1] / 2;
    const int* src = ei;
    const int* dst = ei + Ee;

    float *agg, *zbuf, *h0, *h1, *wt;
    int *offs, *cursor, *ssrc, *bsum;
    cudaGetSymbolAddress((void**)&agg,    g_agg);
    cudaGetSymbolAddress((void**)&zbuf,   g_z);
    cudaGetSymbolAddress((void**)&h0,     g_h0);
    cudaGetSymbolAddress((void**)&h1,     g_h1);
    cudaGetSymbolAddress((void**)&offs,   g_offs);
    cudaGetSymbolAddress((void**)&cursor, g_cursor);
    cudaGetSymbolAddress((void**)&ssrc,   g_ssrc);
    cudaGetSymbolAddress((void**)&bsum,   g_bsum);
    cudaGetSymbolAddress((void**)&wt,     g_wt);
    float* hbuf[2] = {h0, h1};

    cudaFuncSetAttribute(gemm_tc_kernel<true>,
                         cudaFuncAttributeMaxDynamicSharedMemorySize, GEMM_SMEM_BYTES);
    cudaFuncSetAttribute(gemm_tc_kernel<false>,
                         cudaFuncAttributeMaxDynamicSharedMemorySize, GEMM_SMEM_BYTES);

    // --- Pre-round all 6 weight matrices in ONE launch ---
    round_w6_kernel<<<(6 * HDIM * HDIM + 255) / 256, 256>>>(
        wt, Wsrc[0], Wsrc[1], Wsrc[2], Wsrc[3], Wsrc[4], Wsrc[5]);

    // --- Build CSR (dst-sorted src list) ---
    const int nb = (Nn + 1023) / 1024;
    zero_int_kernel<<<(Nn + 255) / 256, 256>>>(cursor, Nn);
    hist_kernel<<<(Ee + 255) / 256, 256>>>(dst, cursor, Ee);
    scan1_kernel<<<nb, 1024>>>(cursor, offs, bsum, Nn);
    scan2_kernel<<<1, NB_MAX>>>(bsum, nb);
    scan3_kernel<<<nb, 1024>>>(offs, cursor, bsum, Nn, nb);
    permute_kernel<<<(Ee + 255) / 256, 256>>>(src, dst, cursor, ssrc, Ee);

    const int gm_blocks   = (Nn + 127) / 128;
    const int ga_blocks   = (Nn + 7) / 8;
    const int pool_blocks = (Nn + 7) / 8;

    const float* hin = x;
    for (int layer = 0; layer < 3; layer++) {
        float* hout = hbuf[layer & 1];
        const float* w1 = wt + (size_t)(2 * layer)     * HDIM * HDIM;
        const float* w2 = wt + (size_t)(2 * layer + 1) * HDIM * HDIM;
        gather_kernel<<<ga_blocks, 256>>>(hin, ssrc, offs, agg, Nn);
        gemm_tc_kernel<true ><<<gm_blocks, 256, GEMM_SMEM_BYTES>>>(agg,  w1, b1[layer], zbuf, Nn);
        gemm_tc_kernel<false><<<gm_blocks, 256, GEMM_SMEM_BYTES>>>(zbuf, w2, b2[layer], hout, Nn);
        hin = hout;
    }

    float* out = (float*)d_out;
    const int zo_blocks = (out_size / 4 + 255) / 256;
    zero_kernel<<<zo_blocks, 256>>>((float4*)out, out_size / 4);
    pool_kernel<<<pool_blocks, 256>>>(hin, batch, out, Nn);
}

// round 11
// speedup vs baseline: 1.1209x; 1.1209x over previous
#include <cuda_runtime.h>
#include <cuda_bf16.h>
#include <cstdint>

#define HDIM 128
#define MAXN 100000
#define MAXE 1600000
#define NB_MAX 128          // max scan blocks: ceil(100000/1024) = 98

// Scratch (device globals; no allocation allowed).
__device__ float g_agg[(size_t)MAXN * HDIM];
__device__ float g_z  [(size_t)MAXN * HDIM];
__device__ float g_h0 [(size_t)MAXN * HDIM];
__device__ float g_h1 [(size_t)MAXN * HDIM];
__device__ int   g_offs[MAXN + 1];
__device__ int   g_cursor[MAXN];
__device__ int   g_ssrc[MAXE];
__device__ int   g_bsum[NB_MAX + 1];
__device__ float g_wt[6][HDIM * HDIM];   // pre-rounded tf32 weights

// GEMM dynamic smem (floats): As0[128*36] Ws0[32*136] As1 Ws1
#define AS_PITCH 36
#define WS_PITCH 136
#define AS_ELEMS (128 * AS_PITCH)
#define WS_ELEMS (32 * WS_PITCH)
#define GEMM_SMEM_BYTES ((AS_ELEMS + WS_ELEMS) * 2 * 4)

// ---------------------------------------------------------------------------
// Helpers
// ---------------------------------------------------------------------------
__device__ __forceinline__ void atomic_add_f4(float4* addr, float4 v) {
#if __CUDA_ARCH__ >= 900
    atomicAdd(addr, v);
#else
    float* f = (float*)addr;
    atomicAdd(f + 0, v.x); atomicAdd(f + 1, v.y);
    atomicAdd(f + 2, v.z); atomicAdd(f + 3, v.w);
#endif
}

__device__ __forceinline__ uint32_t to_tf32(float x) {
    uint32_t r;
    asm("cvt.rna.tf32.f32 %0, %1;" : "=r"(r) : "f"(x));
    return r;
}
__device__ __forceinline__ float round_tf32(float x) {
    return __uint_as_float(to_tf32(x));
}

__device__ __forceinline__ void mma_tf32(float d[4],
                                         uint32_t a0, uint32_t a1, uint32_t a2, uint32_t a3,
                                         uint32_t b0, uint32_t b1) {
    asm volatile(
        "mma.sync.aligned.m16n8k8.row.col.f32.tf32.tf32.f32 "
        "{%0,%1,%2,%3}, {%4,%5,%6,%7}, {%8,%9}, {%0,%1,%2,%3};\n"
        : "+f"(d[0]), "+f"(d[1]), "+f"(d[2]), "+f"(d[3])
        : "r"(a0), "r"(a1), "r"(a2), "r"(a3), "r"(b0), "r"(b1));
}

__device__ __forceinline__ uint32_t smem_u32(const void* p) {
    return (uint32_t)__cvta_generic_to_shared(p);
}
__device__ __forceinline__ void cp_async16(uint32_t saddr, const void* gptr) {
    asm volatile("cp.async.cg.shared.global [%0], [%1], 16;\n" :: "r"(saddr), "l"(gptr));
}
__device__ __forceinline__ void cp_commit() {
    asm volatile("cp.async.commit_group;\n");
}
template <int N>
__device__ __forceinline__ void cp_wait() {
    asm volatile("cp.async.wait_group %0;\n" :: "n"(N));
}

// ---------------------------------------------------------------------------
// Fused weight pre-round: all 6 weight matrices in one launch.
// ---------------------------------------------------------------------------
__global__ void round_w6_kernel(float* __restrict__ dst,
                                const float* __restrict__ w0, const float* __restrict__ w1,
                                const float* __restrict__ w2, const float* __restrict__ w3,
                                const float* __restrict__ w4, const float* __restrict__ w5) {
    const float* srcs[6] = {w0, w1, w2, w3, w4, w5};
    int i = blockIdx.x * blockDim.x + threadIdx.x;
    const int n = HDIM * HDIM;
    if (i < 6 * n) {
        int m = i / n;
        int j = i - m * n;
        dst[(size_t)m * n + j] = round_tf32(srcs[m][j]);
    }
}

// ---------------------------------------------------------------------------
// CSR build
// ---------------------------------------------------------------------------
__global__ void zero_int_kernel(int* __restrict__ p, int n) {
    int i = blockIdx.x * blockDim.x + threadIdx.x;
    if (i < n) p[i] = 0;
}

__global__ void hist_kernel(const int* __restrict__ dst, int* __restrict__ count, int E) {
    int e = blockIdx.x * blockDim.x + threadIdx.x;
    if (e < E) atomicAdd(&count[__ldg(&dst[e])], 1);
}

__global__ __launch_bounds__(1024) void scan1_kernel(const int* __restrict__ cnt,
                                                     int* __restrict__ offs,
                                                     int* __restrict__ bsum, int N) {
    __shared__ int sh[1024];
    int t = threadIdx.x;
    int i = blockIdx.x * 1024 + t;
    int v = (i < N) ? cnt[i] : 0;
    sh[t] = v;
    __syncthreads();
    for (int d = 1; d < 1024; d <<= 1) {
        int x = (t >= d) ? sh[t - d] : 0;
        __syncthreads();
        if (t >= d) sh[t] += x;
        __syncthreads();
    }
    if (i < N) offs[i] = sh[t] - v;
    if (t == 1023) bsum[blockIdx.x] = sh[1023];
}

__global__ __launch_bounds__(NB_MAX) void scan2_kernel(int* __restrict__ bsum, int nb) {
    __shared__ int sh[NB_MAX];
    int t = threadIdx.x;
    int v = (t < nb) ? bsum[t] : 0;
    sh[t] = v;
    __syncthreads();
    for (int d = 1; d < NB_MAX; d <<= 1) {
        int x = (t >= d) ? sh[t - d] : 0;
        __syncthreads();
        if (t >= d) sh[t] += x;
        __syncthreads();
    }
    if (t < nb) bsum[t] = sh[t] - v;
    if (t == 0) bsum[nb] = sh[nb - 1];
}

__global__ __launch_bounds__(1024) void scan3_kernel(int* __restrict__ offs,
                                                     int* __restrict__ cursor,
                                                     const int* __restrict__ bsum,
                                                     int N, int nb) {
    int i = blockIdx.x * 1024 + threadIdx.x;
    if (i < N) {
        int v = offs[i] + bsum[blockIdx.x];
        offs[i] = v;
        cursor[i] = v;
    }
    if (i == 0) offs[N] = bsum[nb];
}

__global__ void permute_kernel(const int* __restrict__ src,
                               const int* __restrict__ dst,
                               int* __restrict__ cursor,
                               int* __restrict__ ssrc, int E) {
    int e = blockIdx.x * blockDim.x + threadIdx.x;
    if (e >= E) return;
    int d = __ldg(&dst[e]);
    int pos = atomicAdd(&cursor[d], 1);
    ssrc[pos] = __ldg(&src[e]);
}

// ---------------------------------------------------------------------------
// Gather: agg[n,:] = tf32_round( h[n,:] + sum_{e: dst==n} h[src[e],:] )
// 2-way unroll (round-9 form: 4-way regressed via L1tex queue contention).
// ---------------------------------------------------------------------------
__global__ __launch_bounds__(256) void gather_kernel(const float* __restrict__ h,
                                                     const int* __restrict__ ssrc,
                                                     const int* __restrict__ offs,
                                                     float* __restrict__ agg,
                                                     int N) {
    int node = (int)(((size_t)blockIdx.x * blockDim.x + threadIdx.x) >> 5);
    int lane = threadIdx.x & 31;
    if (node >= N) return;
    const float4* hb = (const float4*)h;
    int beg = __ldg(&offs[node]);
    int end = __ldg(&offs[node + 1]);

    float4 v0 = __ldg(hb + (size_t)node * 32 + lane);
    float4 v1 = make_float4(0.f, 0.f, 0.f, 0.f);
    int i = beg;
    for (; i + 1 < end; i += 2) {
        int s0 = __ldg(&ssrc[i]);
        int s1 = __ldg(&ssrc[i + 1]);
        float4 a = __ldg(hb + (size_t)s0 * 32 + lane);
        float4 b = __ldg(hb + (size_t)s1 * 32 + lane);
        v0.x += a.x; v0.y += a.y; v0.z += a.z; v0.w += a.w;
        v1.x += b.x; v1.y += b.y; v1.z += b.z; v1.w += b.w;
    }
    if (i < end) {
        int s0 = __ldg(&ssrc[i]);
        float4 a = __ldg(hb + (size_t)s0 * 32 + lane);
        v0.x += a.x; v0.y += a.y; v0.z += a.z; v0.w += a.w;
    }
    v0.x = round_tf32(v0.x + v1.x);
    v0.y = round_tf32(v0.y + v1.y);
    v0.z = round_tf32(v0.z + v1.z);
    v0.w = round_tf32(v0.w + v1.w);
    ((float4*)agg)[(size_t)node * 32 + lane] = v0;
}

// ---------------------------------------------------------------------------
// Tensor-core GEMM, cp.async double-buffered; inputs pre-rounded tf32,
// zero cvt in the inner loop. ROUND_OUT rounds the stored output (for z).
// ---------------------------------------------------------------------------
__device__ __forceinline__ void gemm_load_stage(
    const float* __restrict__ A, const float* __restrict__ W,
    float* As, float* Ws, int rowBase, int kc, int M, int tid) {
#pragma unroll
    for (int i = tid; i < 1024; i += 256) {
        int r  = i >> 3;
        int c4 = (i & 7) * 4;
        int gr = rowBase + r;
        float* dst = &As[r * AS_PITCH + c4];
        if (gr < M) {
            cp_async16(smem_u32(dst), &A[(size_t)gr * HDIM + kc + c4]);
        } else {
            *(float4*)dst = make_float4(0.f, 0.f, 0.f, 0.f);
        }
    }
#pragma unroll
    for (int i = tid; i < 1024; i += 256) {
        int r  = i >> 5;
        int c4 = (i & 31) * 4;
        cp_async16(smem_u32(&Ws[r * WS_PITCH + c4]), &W[(size_t)(kc + r) * HDIM + c4]);
    }
}

template <bool ROUND_OUT>
__global__ __launch_bounds__(256) void gemm_tc_kernel(
    const float* __restrict__ A,
    const float* __restrict__ W,
    const float* __restrict__ bias,
    float* __restrict__ C,
    int M) {
    extern __shared__ float smem[];
    float* Asb[2] = {smem, smem + AS_ELEMS + WS_ELEMS};
    float* Wsb[2] = {smem + AS_ELEMS, smem + 2 * AS_ELEMS + WS_ELEMS};

    const int tid  = threadIdx.x;
    const int lane = tid & 31;
    const int wid  = tid >> 5;
    const int warp_m = (wid & 3) * 32;
    const int warp_n = (wid >> 2) * 64;
    const int g = lane >> 2;
    const int c = lane & 3;
    const int rowBase = blockIdx.x * 128;

    float acc[2][8][4];
#pragma unroll
    for (int mt = 0; mt < 2; mt++)
#pragma unroll
        for (int nt = 0; nt < 8; nt++)
#pragma unroll
            for (int j = 0; j < 4; j++) acc[mt][nt][j] = 0.f;

    gemm_load_stage(A, W, Asb[0], Wsb[0], rowBase, 0, M, tid);
    cp_commit();

#pragma unroll
    for (int ci = 0; ci < 4; ci++) {
        if (ci < 3) {
            gemm_load_stage(A, W, Asb[(ci + 1) & 1], Wsb[(ci + 1) & 1],
                            rowBase, (ci + 1) * 32, M, tid);
            cp_commit();
            cp_wait<1>();
        } else {
            cp_wait<0>();
        }
        __syncthreads();

        const uint32_t* As = (const uint32_t*)Asb[ci & 1];
        const uint32_t* Ws = (const uint32_t*)Wsb[ci & 1];
#pragma unroll
        for (int ks = 0; ks < 4; ks++) {
            const int k0 = ks * 8;
            uint32_t a[2][4];
#pragma unroll
            for (int mt = 0; mt < 2; mt++) {
                int rb = warp_m + mt * 16;
                a[mt][0] = As[(rb + g    ) * AS_PITCH + k0 + c    ];
                a[mt][1] = As[(rb + 8 + g) * AS_PITCH + k0 + c    ];
                a[mt][2] = As[(rb + g    ) * AS_PITCH + k0 + c + 4];
                a[mt][3] = As[(rb + 8 + g) * AS_PITCH + k0 + c + 4];
            }
#pragma unroll
            for (int nt = 0; nt < 8; nt++) {
                int n = warp_n + nt * 8 + g;
                uint32_t b0 = Ws[(k0 + c    ) * WS_PITCH + n];
                uint32_t b1 = Ws[(k0 + 4 + c) * WS_PITCH + n];
#pragma unroll
                for (int mt = 0; mt < 2; mt++)
                    mma_tf32(acc[mt][nt], a[mt][0], a[mt][1], a[mt][2], a[mt][3], b0, b1);
            }
        }
        __syncthreads();
    }

#pragma unroll
    for (int nt = 0; nt < 8; nt++) {
        int col = warp_n + nt * 8 + 2 * c;
        float2 bb = *(const float2*)&bias[col];
#pragma unroll
        for (int mt = 0; mt < 2; mt++) {
            int row0 = rowBase + warp_m + mt * 16 + g;
            int row1 = row0 + 8;
            if (row0 < M) {
                float2 o;
                o.x = fmaxf(acc[mt][nt][0] + bb.x, 0.f);
                o.y = fmaxf(acc[mt][nt][1] + bb.y, 0.f);
                if (ROUND_OUT) { o.x = round_tf32(o.x); o.y = round_tf32(o.y); }
                *(float2*)&C[(size_t)row0 * HDIM + col] = o;
            }
            if (row1 < M) {
                float2 o;
                o.x = fmaxf(acc[mt][nt][2] + bb.x, 0.f);
                o.y = fmaxf(acc[mt][nt][3] + bb.y, 0.f);
                if (ROUND_OUT) { o.x = round_tf32(o.x); o.y = round_tf32(o.y); }
                *(float2*)&C[(size_t)row1 * HDIM + col] = o;
            }
        }
    }
}

// ---------------------------------------------------------------------------
// Final zero + pool
// ---------------------------------------------------------------------------
__global__ void zero_kernel(float4* __restrict__ p, size_t n4) {
    size_t i = (size_t)blockIdx.x * blockDim.x + threadIdx.x;
    if (i < n4) p[i] = make_float4(0.f, 0.f, 0.f, 0.f);
}

__global__ void pool_kernel(const float* __restrict__ h,
                            const int* __restrict__ batch,
                            float* __restrict__ out,
                            int M) {
    int warp = (int)(((size_t)blockIdx.x * blockDim.x + threadIdx.x) >> 5);
    int lane = threadIdx.x & 31;
    if (warp >= M) return;
    int g = __ldg(&batch[warp]);
    float4 v = __ldg(((const float4*)(h + (size_t)warp * HDIM)) + lane);
    atomic_add_f4(((float4*)(out + (size_t)g * HDIM)) + lane, v);
}

// ---------------------------------------------------------------------------
// Launch
// ---------------------------------------------------------------------------
extern "C" void kernel_launch(void* const* d_in, const int* in_sizes, int n_in,
                              void* d_out, int out_size) {
    const float* x     = (const float*)d_in[0];
    const int*   ei    = (const int*)d_in[1];
    const int*   batch = (const int*)d_in[2];
    const float* Wsrc[6] = {(const float*)d_in[3], (const float*)d_in[5],
                            (const float*)d_in[7], (const float*)d_in[9],
                            (const float*)d_in[11], (const float*)d_in[13]};
    const float* b1[3] = {(const float*)d_in[4], (const float*)d_in[8],  (const float*)d_in[12]};
    const float* b2[3] = {(const float*)d_in[6], (const float*)d_in[10], (const float*)d_in[14]};

    const int Nn = in_sizes[0] / HDIM;
    const int Ee = in_sizes[1] / 2;
    const int* src = ei;
    const int* dst = ei + Ee;

    float *agg, *zbuf, *h0, *h1, *wt;
    int *offs, *cursor, *ssrc, *bsum;
    cudaGetSymbolAddress((void**)&agg,    g_agg);
    cudaGetSymbolAddress((void**)&zbuf,   g_z);
    cudaGetSymbolAddress((void**)&h0,     g_h0);
    cudaGetSymbolAddress((void**)&h1,     g_h1);
    cudaGetSymbolAddress((void**)&offs,   g_offs);
    cudaGetSymbolAddress((void**)&cursor, g_cursor);
    cudaGetSymbolAddress((void**)&ssrc,   g_ssrc);
    cudaGetSymbolAddress((void**)&bsum,   g_bsum);
    cudaGetSymbolAddress((void**)&wt,     g_wt);
    float* hbuf[2] = {h0, h1};

    cudaFuncSetAttribute(gemm_tc_kernel<true>,
                         cudaFuncAttributeMaxDynamicSharedMemorySize, GEMM_SMEM_BYTES);
    cudaFuncSetAttribute(gemm_tc_kernel<false>,
                         cudaFuncAttributeMaxDynamicSharedMemorySize, GEMM_SMEM_BYTES);

    // --- Pre-round all 6 weight matrices in ONE launch ---
    round_w6_kernel<<<(6 * HDIM * HDIM + 255) / 256, 256>>>(
        wt, Wsrc[0], Wsrc[1], Wsrc[2], Wsrc[3], Wsrc[4], Wsrc[5]);

    // --- Build CSR (dst-sorted src list) ---
    const int nb = (Nn + 1023) / 1024;
    zero_int_kernel<<<(Nn + 255) / 256, 256>>>(cursor, Nn);
    hist_kernel<<<(Ee + 255) / 256, 256>>>(dst, cursor, Ee);
    scan1_kernel<<<nb, 1024>>>(cursor, offs, bsum, Nn);
    scan2_kernel<<<1, NB_MAX>>>(bsum, nb);
    scan3_kernel<<<nb, 1024>>>(offs, cursor, bsum, Nn, nb);
    permute_kernel<<<(Ee + 255) / 256, 256>>>(src, dst, cursor, ssrc, Ee);

    const int gm_blocks   = (Nn + 127) / 128;
    const int ga_blocks   = (Nn + 7) / 8;
    const int pool_blocks = (Nn + 7) / 8;

    const float* hin = x;
    for (int layer = 0; layer < 3; layer++) {
        float* hout = hbuf[layer & 1];
        const float* w1 = wt + (size_t)(2 * layer)     * HDIM * HDIM;
        const float* w2 = wt + (size_t)(2 * layer + 1) * HDIM * HDIM;
        gather_kernel<<<ga_blocks, 256>>>(hin, ssrc, offs, agg, Nn);
        gemm_tc_kernel<true ><<<gm_blocks, 256, GEMM_SMEM_BYTES>>>(agg,  w1, b1[layer], zbuf, Nn);
        gemm_tc_kernel<false><<<gm_blocks, 256, GEMM_SMEM_BYTES>>>(zbuf, w2, b2[layer], hout, Nn);
        hin = hout;
    }

    float* out = (float*)d_out;
    const int zo_blocks = (out_size / 4 + 255) / 256;
    zero_kernel<<<zo_blocks, 256>>>((float4*)out, out_size / 4);
    pool_kernel<<<pool_blocks, 256>>>(hin, batch, out, Nn);
}

// round 12
// speedup vs baseline: 1.2294x; 1.0968x over previous
#include <cuda_runtime.h>
#include <cuda_bf16.h>
#include <cuda_fp16.h>
#include <cstdint>

#define HDIM 128
#define MAXN 100000
#define MAXE 1600000
#define NB_MAX 128          // max scan blocks: ceil(100000/1024) = 98

// Scratch (device globals; no allocation allowed).
__device__ float  g_agg[(size_t)MAXN * HDIM];
__device__ float  g_z  [(size_t)MAXN * HDIM];
__device__ __half g_h0h[(size_t)MAXN * HDIM];
__device__ __half g_h1h[(size_t)MAXN * HDIM];
__device__ int    g_offs[MAXN + 1];
__device__ int    g_cursor[MAXN];
__device__ int    g_ssrc[MAXE];
__device__ int    g_bsum[NB_MAX + 1];
__device__ float  g_wt[6][HDIM * HDIM];   // pre-rounded tf32 weights

// GEMM dynamic smem (floats): As0[128*36] Ws0[32*136] As1 Ws1
#define AS_PITCH 36
#define WS_PITCH 136
#define AS_ELEMS (128 * AS_PITCH)
#define WS_ELEMS (32 * WS_PITCH)
#define GEMM_SMEM_BYTES ((AS_ELEMS + WS_ELEMS) * 2 * 4)

// ---------------------------------------------------------------------------
// Helpers
// ---------------------------------------------------------------------------
__device__ __forceinline__ void atomic_add_f4(float4* addr, float4 v) {
#if __CUDA_ARCH__ >= 900
    atomicAdd(addr, v);
#else
    float* f = (float*)addr;
    atomicAdd(f + 0, v.x); atomicAdd(f + 1, v.y);
    atomicAdd(f + 2, v.z); atomicAdd(f + 3, v.w);
#endif
}

__device__ __forceinline__ uint32_t to_tf32(float x) {
    uint32_t r;
    asm("cvt.rna.tf32.f32 %0, %1;" : "=r"(r) : "f"(x));
    return r;
}
__device__ __forceinline__ float round_tf32(float x) {
    return __uint_as_float(to_tf32(x));
}

__device__ __forceinline__ void mma_tf32(float d[4],
                                         uint32_t a0, uint32_t a1, uint32_t a2, uint32_t a3,
                                         uint32_t b0, uint32_t b1) {
    asm volatile(
        "mma.sync.aligned.m16n8k8.row.col.f32.tf32.tf32.f32 "
        "{%0,%1,%2,%3}, {%4,%5,%6,%7}, {%8,%9}, {%0,%1,%2,%3};\n"
        : "+f"(d[0]), "+f"(d[1]), "+f"(d[2]), "+f"(d[3])
        : "r"(a0), "r"(a1), "r"(a2), "r"(a3), "r"(b0), "r"(b1));
}

__device__ __forceinline__ uint32_t smem_u32(const void* p) {
    return (uint32_t)__cvta_generic_to_shared(p);
}
__device__ __forceinline__ void cp_async16(uint32_t saddr, const void* gptr) {
    asm volatile("cp.async.cg.shared.global [%0], [%1], 16;\n" :: "r"(saddr), "l"(gptr));
}
__device__ __forceinline__ void cp_commit() {
    asm volatile("cp.async.commit_group;\n");
}
template <int N>
__device__ __forceinline__ void cp_wait() {
    asm volatile("cp.async.wait_group %0;\n" :: "n"(N));
}

// unpack uint2 (4 halves) -> float4
__device__ __forceinline__ float4 half4_to_float4(uint2 u) {
    __half2 p0 = *(__half2*)&u.x;
    __half2 p1 = *(__half2*)&u.y;
    float2 f0 = __half22float2(p0);
    float2 f1 = __half22float2(p1);
    return make_float4(f0.x, f0.y, f1.x, f1.y);
}

// ---------------------------------------------------------------------------
// Fused weight pre-round: all 6 weight matrices in one launch.
// ---------------------------------------------------------------------------
__global__ void round_w6_kernel(float* __restrict__ dst,
                                const float* __restrict__ w0, const float* __restrict__ w1,
                                const float* __restrict__ w2, const float* __restrict__ w3,
                                const float* __restrict__ w4, const float* __restrict__ w5) {
    const float* srcs[6] = {w0, w1, w2, w3, w4, w5};
    int i = blockIdx.x * blockDim.x + threadIdx.x;
    const int n = HDIM * HDIM;
    if (i < 6 * n) {
        int m = i / n;
        int j = i - m * n;
        dst[(size_t)m * n + j] = round_tf32(srcs[m][j]);
    }
}

// ---------------------------------------------------------------------------
// CSR build
// ---------------------------------------------------------------------------
__global__ void zero_int_kernel(int* __restrict__ p, int n) {
    int i = blockIdx.x * blockDim.x + threadIdx.x;
    if (i < n) p[i] = 0;
}

__global__ void hist_kernel(const int* __restrict__ dst, int* __restrict__ count, int E) {
    int e = blockIdx.x * blockDim.x + threadIdx.x;
    if (e < E) atomicAdd(&count[__ldg(&dst[e])], 1);
}

__global__ __launch_bounds__(1024) void scan1_kernel(const int* __restrict__ cnt,
                                                     int* __restrict__ offs,
                                                     int* __restrict__ bsum, int N) {
    __shared__ int sh[1024];
    int t = threadIdx.x;
    int i = blockIdx.x * 1024 + t;
    int v = (i < N) ? cnt[i] : 0;
    sh[t] = v;
    __syncthreads();
    for (int d = 1; d < 1024; d <<= 1) {
        int x = (t >= d) ? sh[t - d] : 0;
        __syncthreads();
        if (t >= d) sh[t] += x;
        __syncthreads();
    }
    if (i < N) offs[i] = sh[t] - v;
    if (t == 1023) bsum[blockIdx.x] = sh[1023];
}

__global__ __launch_bounds__(NB_MAX) void scan2_kernel(int* __restrict__ bsum, int nb) {
    __shared__ int sh[NB_MAX];
    int t = threadIdx.x;
    int v = (t < nb) ? bsum[t] : 0;
    sh[t] = v;
    __syncthreads();
    for (int d = 1; d < NB_MAX; d <<= 1) {
        int x = (t >= d) ? sh[t - d] : 0;
        __syncthreads();
        if (t >= d) sh[t] += x;
        __syncthreads();
    }
    if (t < nb) bsum[t] = sh[t] - v;
    if (t == 0) bsum[nb] = sh[nb - 1];
}

__global__ __launch_bounds__(1024) void scan3_kernel(int* __restrict__ offs,
                                                     int* __restrict__ cursor,
                                                     const int* __restrict__ bsum,
                                                     int N, int nb) {
    int i = blockIdx.x * 1024 + threadIdx.x;
    if (i < N) {
        int v = offs[i] + bsum[blockIdx.x];
        offs[i] = v;
        cursor[i] = v;
    }
    if (i == 0) offs[N] = bsum[nb];
}

__global__ void permute_kernel(const int* __restrict__ src,
                               const int* __restrict__ dst,
                               int* __restrict__ cursor,
                               int* __restrict__ ssrc, int E) {
    int e = blockIdx.x * blockDim.x + threadIdx.x;
    if (e >= E) return;
    int d = __ldg(&dst[e]);
    int pos = atomicAdd(&cursor[d], 1);
    ssrc[pos] = __ldg(&src[e]);
}

// ---------------------------------------------------------------------------
// Gather (fp32 source): layer 1, reads x. 2-way unroll (proven form).
// agg[n,:] = tf32_round( h[n,:] + sum h[src,:] )
// ---------------------------------------------------------------------------
__global__ __launch_bounds__(256) void gather_f32_kernel(const float* __restrict__ h,
                                                         const int* __restrict__ ssrc,
                                                         const int* __restrict__ offs,
                                                         float* __restrict__ agg,
                                                         int N) {
    int node = (int)(((size_t)blockIdx.x * blockDim.x + threadIdx.x) >> 5);
    int lane = threadIdx.x & 31;
    if (node >= N) return;
    const float4* hb = (const float4*)h;
    int beg = __ldg(&offs[node]);
    int end = __ldg(&offs[node + 1]);

    float4 v0 = __ldg(hb + (size_t)node * 32 + lane);
    float4 v1 = make_float4(0.f, 0.f, 0.f, 0.f);
    int i = beg;
    for (; i + 1 < end; i += 2) {
        int s0 = __ldg(&ssrc[i]);
        int s1 = __ldg(&ssrc[i + 1]);
        float4 a = __ldg(hb + (size_t)s0 * 32 + lane);
        float4 b = __ldg(hb + (size_t)s1 * 32 + lane);
        v0.x += a.x; v0.y += a.y; v0.z += a.z; v0.w += a.w;
        v1.x += b.x; v1.y += b.y; v1.z += b.z; v1.w += b.w;
    }
    if (i < end) {
        int s0 = __ldg(&ssrc[i]);
        float4 a = __ldg(hb + (size_t)s0 * 32 + lane);
        v0.x += a.x; v0.y += a.y; v0.z += a.z; v0.w += a.w;
    }
    v0.x = round_tf32(v0.x + v1.x);
    v0.y = round_tf32(v0.y + v1.y);
    v0.z = round_tf32(v0.z + v1.z);
    v0.w = round_tf32(v0.w + v1.w);
    ((float4*)agg)[(size_t)node * 32 + lane] = v0;
}

// ---------------------------------------------------------------------------
// Gather (fp16 source): layers 2-3, reads fp16 h. Row = 32 x uint2 (8B/lane).
// ---------------------------------------------------------------------------
__global__ __launch_bounds__(256) void gather_f16_kernel(const __half* __restrict__ h,
                                                         const int* __restrict__ ssrc,
                                                         const int* __restrict__ offs,
                                                         float* __restrict__ agg,
                                                         int N) {
    int node = (int)(((size_t)blockIdx.x * blockDim.x + threadIdx.x) >> 5);
    int lane = threadIdx.x & 31;
    if (node >= N) return;
    const uint2* hb = (const uint2*)h;
    int beg = __ldg(&offs[node]);
    int end = __ldg(&offs[node + 1]);

    float4 v0 = half4_to_float4(__ldg(hb + (size_t)node * 32 + lane));
    float4 v1 = make_float4(0.f, 0.f, 0.f, 0.f);
    int i = beg;
    for (; i + 1 < end; i += 2) {
        int s0 = __ldg(&ssrc[i]);
        int s1 = __ldg(&ssrc[i + 1]);
        float4 a = half4_to_float4(__ldg(hb + (size_t)s0 * 32 + lane));
        float4 b = half4_to_float4(__ldg(hb + (size_t)s1 * 32 + lane));
        v0.x += a.x; v0.y += a.y; v0.z += a.z; v0.w += a.w;
        v1.x += b.x; v1.y += b.y; v1.z += b.z; v1.w += b.w;
    }
    if (i < end) {
        int s0 = __ldg(&ssrc[i]);
        float4 a = half4_to_float4(__ldg(hb + (size_t)s0 * 32 + lane));
        v0.x += a.x; v0.y += a.y; v0.z += a.z; v0.w += a.w;
    }
    v0.x = round_tf32(v0.x + v1.x);
    v0.y = round_tf32(v0.y + v1.y);
    v0.z = round_tf32(v0.z + v1.z);
    v0.w = round_tf32(v0.w + v1.w);
    ((float4*)agg)[(size_t)node * 32 + lane] = v0;
}

// ---------------------------------------------------------------------------
// Tensor-core GEMM, cp.async double-buffered; inputs pre-rounded tf32.
// ROUND_OUT: tf32-round stored output (z path). OUT_HALF: store fp16 (h path).
// ---------------------------------------------------------------------------
__device__ __forceinline__ void gemm_load_stage(
    const float* __restrict__ A, const float* __restrict__ W,
    float* As, float* Ws, int rowBase, int kc, int M, int tid) {
#pragma unroll
    for (int i = tid; i < 1024; i += 256) {
        int r  = i >> 3;
        int c4 = (i & 7) * 4;
        int gr = rowBase + r;
        float* dst = &As[r * AS_PITCH + c4];
        if (gr < M) {
            cp_async16(smem_u32(dst), &A[(size_t)gr * HDIM + kc + c4]);
        } else {
            *(float4*)dst = make_float4(0.f, 0.f, 0.f, 0.f);
        }
    }
#pragma unroll
    for (int i = tid; i < 1024; i += 256) {
        int r  = i >> 5;
        int c4 = (i & 31) * 4;
        cp_async16(smem_u32(&Ws[r * WS_PITCH + c4]), &W[(size_t)(kc + r) * HDIM + c4]);
    }
}

template <bool ROUND_OUT, bool OUT_HALF>
__global__ __launch_bounds__(256) void gemm_tc_kernel(
    const float* __restrict__ A,
    const float* __restrict__ W,
    const float* __restrict__ bias,
    void* __restrict__ Cout,
    int M) {
    extern __shared__ float smem[];
    float* Asb[2] = {smem, smem + AS_ELEMS + WS_ELEMS};
    float* Wsb[2] = {smem + AS_ELEMS, smem + 2 * AS_ELEMS + WS_ELEMS};

    const int tid  = threadIdx.x;
    const int lane = tid & 31;
    const int wid  = tid >> 5;
    const int warp_m = (wid & 3) * 32;
    const int warp_n = (wid >> 2) * 64;
    const int g = lane >> 2;
    const int c = lane & 3;
    const int rowBase = blockIdx.x * 128;

    float acc[2][8][4];
#pragma unroll
    for (int mt = 0; mt < 2; mt++)
#pragma unroll
        for (int nt = 0; nt < 8; nt++)
#pragma unroll
            for (int j = 0; j < 4; j++) acc[mt][nt][j] = 0.f;

    gemm_load_stage(A, W, Asb[0], Wsb[0], rowBase, 0, M, tid);
    cp_commit();

#pragma unroll
    for (int ci = 0; ci < 4; ci++) {
        if (ci < 3) {
            gemm_load_stage(A, W, Asb[(ci + 1) & 1], Wsb[(ci + 1) & 1],
                            rowBase, (ci + 1) * 32, M, tid);
            cp_commit();
            cp_wait<1>();
        } else {
            cp_wait<0>();
        }
        __syncthreads();

        const uint32_t* As = (const uint32_t*)Asb[ci & 1];
        const uint32_t* Ws = (const uint32_t*)Wsb[ci & 1];
#pragma unroll
        for (int ks = 0; ks < 4; ks++) {
            const int k0 = ks * 8;
            uint32_t a[2][4];
#pragma unroll
            for (int mt = 0; mt < 2; mt++) {
                int rb = warp_m + mt * 16;
                a[mt][0] = As[(rb + g    ) * AS_PITCH + k0 + c    ];
                a[mt][1] = As[(rb + 8 + g) * AS_PITCH + k0 + c    ];
                a[mt][2] = As[(rb + g    ) * AS_PITCH + k0 + c + 4];
                a[mt][3] = As[(rb + 8 + g) * AS_PITCH + k0 + c + 4];
            }
#pragma unroll
            for (int nt = 0; nt < 8; nt++) {
                int n = warp_n + nt * 8 + g;
                uint32_t b0 = Ws[(k0 + c    ) * WS_PITCH + n];
                uint32_t b1 = Ws[(k0 + 4 + c) * WS_PITCH + n];
#pragma unroll
                for (int mt = 0; mt < 2; mt++)
                    mma_tf32(acc[mt][nt], a[mt][0], a[mt][1], a[mt][2], a[mt][3], b0, b1);
            }
        }
        __syncthreads();
    }

#pragma unroll
    for (int nt = 0; nt < 8; nt++) {
        int col = warp_n + nt * 8 + 2 * c;
        float2 bb = *(const float2*)&bias[col];
#pragma unroll
        for (int mt = 0; mt < 2; mt++) {
            int row0 = rowBase + warp_m + mt * 16 + g;
            int row1 = row0 + 8;
            float2 o0, o1;
            o0.x = fmaxf(acc[mt][nt][0] + bb.x, 0.f);
            o0.y = fmaxf(acc[mt][nt][1] + bb.y, 0.f);
            o1.x = fmaxf(acc[mt][nt][2] + bb.x, 0.f);
            o1.y = fmaxf(acc[mt][nt][3] + bb.y, 0.f);
            if (ROUND_OUT) {
                o0.x = round_tf32(o0.x); o0.y = round_tf32(o0.y);
                o1.x = round_tf32(o1.x); o1.y = round_tf32(o1.y);
            }
            if (OUT_HALF) {
                __half2* Ch = (__half2*)Cout;
                if (row0 < M) Ch[((size_t)row0 * HDIM + col) >> 1] = __floats2half2_rn(o0.x, o0.y);
                if (row1 < M) Ch[((size_t)row1 * HDIM + col) >> 1] = __floats2half2_rn(o1.x, o1.y);
            } else {
                float* Cf = (float*)Cout;
                if (row0 < M) *(float2*)&Cf[(size_t)row0 * HDIM + col] = o0;
                if (row1 < M) *(float2*)&Cf[(size_t)row1 * HDIM + col] = o1;
            }
        }
    }
}

// ---------------------------------------------------------------------------
// Final zero + pool (pool reads fp16 h, accumulates fp32 atomics)
// ---------------------------------------------------------------------------
__global__ void zero_kernel(float4* __restrict__ p, size_t n4) {
    size_t i = (size_t)blockIdx.x * blockDim.x + threadIdx.x;
    if (i < n4) p[i] = make_float4(0.f, 0.f, 0.f, 0.f);
}

__global__ void pool_kernel(const __half* __restrict__ h,
                            const int* __restrict__ batch,
                            float* __restrict__ out,
                            int M) {
    int warp = (int)(((size_t)blockIdx.x * blockDim.x + threadIdx.x) >> 5);
    int lane = threadIdx.x & 31;
    if (warp >= M) return;
    int g = __ldg(&batch[warp]);
    float4 v = half4_to_float4(__ldg(((const uint2*)h) + (size_t)warp * 32 + lane));
    atomic_add_f4(((float4*)(out + (size_t)g * HDIM)) + lane, v);
}

// ---------------------------------------------------------------------------
// Launch
// ---------------------------------------------------------------------------
extern "C" void kernel_launch(void* const* d_in, const int* in_sizes, int n_in,
                              void* d_out, int out_size) {
    const float* x     = (const float*)d_in[0];
    const int*   ei    = (const int*)d_in[1];
    const int*   batch = (const int*)d_in[2];
    const float* Wsrc[6] = {(const float*)d_in[3], (const float*)d_in[5],
                            (const float*)d_in[7], (const float*)d_in[9],
                            (const float*)d_in[11], (const float*)d_in[13]};
    const float* b1[3] = {(const float*)d_in[4], (const float*)d_in[8],  (const float*)d_in[12]};
    const float* b2[3] = {(const float*)d_in[6], (const float*)d_in[10], (const float*)d_in[14]};

    const int Nn = in_sizes[0] / HDIM;
    const int Ee = in_sizes[1] / 2;
    const int* src = ei;
    const int* dst = ei + Ee;

    float *agg, *zbuf, *wt;
    __half *h0, *h1;
    int *offs, *cursor, *ssrc, *bsum;
    cudaGetSymbolAddress((void**)&agg,    g_agg);
    cudaGetSymbolAddress((void**)&zbuf,   g_z);
    cudaGetSymbolAddress((void**)&h0,     g_h0h);
    cudaGetSymbolAddress((void**)&h1,     g_h1h);
    cudaGetSymbolAddress((void**)&offs,   g_offs);
    cudaGetSymbolAddress((void**)&cursor, g_cursor);
    cudaGetSymbolAddress((void**)&ssrc,   g_ssrc);
    cudaGetSymbolAddress((void**)&bsum,   g_bsum);
    cudaGetSymbolAddress((void**)&wt,     g_wt);
    __half* hbuf[2] = {h0, h1};

    cudaFuncSetAttribute(gemm_tc_kernel<true, false>,
                         cudaFuncAttributeMaxDynamicSharedMemorySize, GEMM_SMEM_BYTES);
    cudaFuncSetAttribute(gemm_tc_kernel<false, true>,
                         cudaFuncAttributeMaxDynamicSharedMemorySize, GEMM_SMEM_BYTES);

    // --- Pre-round all 6 weight matrices in ONE launch ---
    round_w6_kernel<<<(6 * HDIM * HDIM + 255) / 256, 256>>>(
        wt, Wsrc[0], Wsrc[1], Wsrc[2], Wsrc[3], Wsrc[4], Wsrc[5]);

    // --- Build CSR (dst-sorted src list) ---
    const int nb = (Nn + 1023) / 1024;
    zero_int_kernel<<<(Nn + 255) / 256, 256>>>(cursor, Nn);
    hist_kernel<<<(Ee + 255) / 256, 256>>>(dst, cursor, Ee);
    scan1_kernel<<<nb, 1024>>>(cursor, offs, bsum, Nn);
    scan2_kernel<<<1, NB_MAX>>>(bsum, nb);
    scan3_kernel<<<nb, 1024>>>(offs, cursor, bsum, Nn, nb);
    permute_kernel<<<(Ee + 255) / 256, 256>>>(src, dst, cursor, ssrc, Ee);

    const int gm_blocks   = (Nn + 127) / 128;
    const int ga_blocks   = (Nn + 7) / 8;
    const int pool_blocks = (Nn + 7) / 8;

    const __half* hin_h = nullptr;
    for (int layer = 0; layer < 3; layer++) {
        __half* hout = hbuf[layer & 1];
        const float* w1 = wt + (size_t)(2 * layer)     * HDIM * HDIM;
        const float* w2 = wt + (size_t)(2 * layer + 1) * HDIM * HDIM;
        if (layer == 0)
            gather_f32_kernel<<<ga_blocks, 256>>>(x, ssrc, offs, agg, Nn);
        else
            gather_f16_kernel<<<ga_blocks, 256>>>(hin_h, ssrc, offs, agg, Nn);
        gemm_tc_kernel<true, false><<<gm_blocks, 256, GEMM_SMEM_BYTES>>>(agg,  w1, b1[layer], zbuf, Nn);
        gemm_tc_kernel<false, true><<<gm_blocks, 256, GEMM_SMEM_BYTES>>>(zbuf, w2, b2[layer], hout, Nn);
        hin_h = hout;
    }

    float* out = (float*)d_out;
    const int zo_blocks = (out_size / 4 + 255) / 256;
    zero_kernel<<<zo_blocks, 256>>>((float4*)out, out_size / 4);
    pool_kernel<<<pool_blocks, 256>>>(hin_h, batch, out, Nn);
}

// round 13
// speedup vs baseline: 1.4547x; 1.1833x over previous
#include <cuda_runtime.h>
#include <cuda_bf16.h>
#include <cuda_fp16.h>
#include <cstdint>

#define HDIM 128
#define MAXN 100000
#define MAXE 1600000
#define NB_MAX 128          // max scan blocks: ceil(100000/1024) = 98

// Scratch (device globals; no allocation allowed).
__device__ __half g_agg[(size_t)MAXN * HDIM];
__device__ __half g_z  [(size_t)MAXN * HDIM];
__device__ __half g_h0h[(size_t)MAXN * HDIM];
__device__ __half g_h1h[(size_t)MAXN * HDIM];
__device__ int    g_offs[MAXN + 1];
__device__ int    g_cursor[MAXN];
__device__ int    g_ssrc[MAXE];
__device__ int    g_bsum[NB_MAX + 1];
__device__ __half g_wth[6][HDIM * HDIM];  // fp16 weights, TRANSPOSED: wt[n][k]

// GEMM smem (halves): As[128][136] + Wt[128][136], single stage.
#define T_PITCH 136
#define T_ELEMS (128 * T_PITCH)
#define GEMM_SMEM_BYTES (2 * T_ELEMS * 2)

// ---------------------------------------------------------------------------
// Helpers
// ---------------------------------------------------------------------------
__device__ __forceinline__ void atomic_add_f4(float4* addr, float4 v) {
#if __CUDA_ARCH__ >= 900
    atomicAdd(addr, v);
#else
    float* f = (float*)addr;
    atomicAdd(f + 0, v.x); atomicAdd(f + 1, v.y);
    atomicAdd(f + 2, v.z); atomicAdd(f + 3, v.w);
#endif
}

// fp16 mma: D(f32) += A(f16) * B(f16), m16n8k16, A row-major, B col-major
__device__ __forceinline__ void mma_f16(float d[4],
                                        uint32_t a0, uint32_t a1, uint32_t a2, uint32_t a3,
                                        uint32_t b0, uint32_t b1) {
    asm volatile(
        "mma.sync.aligned.m16n8k16.row.col.f32.f16.f16.f32 "
        "{%0,%1,%2,%3}, {%4,%5,%6,%7}, {%8,%9}, {%0,%1,%2,%3};\n"
        : "+f"(d[0]), "+f"(d[1]), "+f"(d[2]), "+f"(d[3])
        : "r"(a0), "r"(a1), "r"(a2), "r"(a3), "r"(b0), "r"(b1));
}

__device__ __forceinline__ uint32_t smem_u32(const void* p) {
    return (uint32_t)__cvta_generic_to_shared(p);
}
__device__ __forceinline__ void cp_async16(uint32_t saddr, const void* gptr) {
    asm volatile("cp.async.cg.shared.global [%0], [%1], 16;\n" :: "r"(saddr), "l"(gptr));
}
__device__ __forceinline__ void cp_commit() {
    asm volatile("cp.async.commit_group;\n");
}
template <int N>
__device__ __forceinline__ void cp_wait() {
    asm volatile("cp.async.wait_group %0;\n" :: "n"(N));
}

// unpack uint2 (4 halves) -> float4
__device__ __forceinline__ float4 half4_to_float4(uint2 u) {
    __half2 p0 = *(__half2*)&u.x;
    __half2 p1 = *(__half2*)&u.y;
    float2 f0 = __half22float2(p0);
    float2 f1 = __half22float2(p1);
    return make_float4(f0.x, f0.y, f1.x, f1.y);
}
__device__ __forceinline__ uint2 float4_to_half4(float4 v) {
    uint2 u;
    *(__half2*)&u.x = __floats2half2_rn(v.x, v.y);
    *(__half2*)&u.y = __floats2half2_rn(v.z, v.w);
    return u;
}

// ---------------------------------------------------------------------------
// Weight prep: convert all 6 to fp16 AND transpose -> wt[m][n*128+k] = W[k][n]
// ---------------------------------------------------------------------------
__global__ void prep_w6_kernel(__half* __restrict__ dst,
                               const float* __restrict__ w0, const float* __restrict__ w1,
                               const float* __restrict__ w2, const float* __restrict__ w3,
                               const float* __restrict__ w4, const float* __restrict__ w5) {
    const float* srcs[6] = {w0, w1, w2, w3, w4, w5};
    int i = blockIdx.x * blockDim.x + threadIdx.x;
    const int n = HDIM * HDIM;
    if (i < 6 * n) {
        int m = i / n;
        int j = i - m * n;          // j = nn*128 + kk (dst index)
        int nn = j >> 7;
        int kk = j & 127;
        dst[(size_t)m * n + j] = __float2half_rn(srcs[m][kk * HDIM + nn]);
    }
}

// ---------------------------------------------------------------------------
// CSR build
// ---------------------------------------------------------------------------
__global__ void zero_int_kernel(int* __restrict__ p, int n) {
    int i = blockIdx.x * blockDim.x + threadIdx.x;
    if (i < n) p[i] = 0;
}

__global__ void hist_kernel(const int* __restrict__ dst, int* __restrict__ count, int E) {
    int e = blockIdx.x * blockDim.x + threadIdx.x;
    if (e < E) atomicAdd(&count[__ldg(&dst[e])], 1);
}

__global__ __launch_bounds__(1024) void scan1_kernel(const int* __restrict__ cnt,
                                                     int* __restrict__ offs,
                                                     int* __restrict__ bsum, int N) {
    __shared__ int sh[1024];
    int t = threadIdx.x;
    int i = blockIdx.x * 1024 + t;
    int v = (i < N) ? cnt[i] : 0;
    sh[t] = v;
    __syncthreads();
    for (int d = 1; d < 1024; d <<= 1) {
        int x = (t >= d) ? sh[t - d] : 0;
        __syncthreads();
        if (t >= d) sh[t] += x;
        __syncthreads();
    }
    if (i < N) offs[i] = sh[t] - v;
    if (t == 1023) bsum[blockIdx.x] = sh[1023];
}

__global__ __launch_bounds__(NB_MAX) void scan2_kernel(int* __restrict__ bsum, int nb) {
    __shared__ int sh[NB_MAX];
    int t = threadIdx.x;
    int v = (t < nb) ? bsum[t] : 0;
    sh[t] = v;
    __syncthreads();
    for (int d = 1; d < NB_MAX; d <<= 1) {
        int x = (t >= d) ? sh[t - d] : 0;
        __syncthreads();
        if (t >= d) sh[t] += x;
        __syncthreads();
    }
    if (t < nb) bsum[t] = sh[t] - v;
    if (t == 0) bsum[nb] = sh[nb - 1];
}

__global__ __launch_bounds__(1024) void scan3_kernel(int* __restrict__ offs,
                                                     int* __restrict__ cursor,
                                                     const int* __restrict__ bsum,
                                                     int N, int nb) {
    int i = blockIdx.x * 1024 + threadIdx.x;
    if (i < N) {
        int v = offs[i] + bsum[blockIdx.x];
        offs[i] = v;
        cursor[i] = v;
    }
    if (i == 0) offs[N] = bsum[nb];
}

__global__ void permute_kernel(const int* __restrict__ src,
                               const int* __restrict__ dst,
                               int* __restrict__ cursor,
                               int* __restrict__ ssrc, int E) {
    int e = blockIdx.x * blockDim.x + threadIdx.x;
    if (e >= E) return;
    int d = __ldg(&dst[e]);
    int pos = atomicAdd(&cursor[d], 1);
    ssrc[pos] = __ldg(&src[e]);
}

// ---------------------------------------------------------------------------
// Gather (fp32 source): layer 1, reads x; writes fp16 agg.
// ---------------------------------------------------------------------------
__global__ __launch_bounds__(256) void gather_f32_kernel(const float* __restrict__ h,
                                                         const int* __restrict__ ssrc,
                                                         const int* __restrict__ offs,
                                                         __half* __restrict__ agg,
                                                         int N) {
    int node = (int)(((size_t)blockIdx.x * blockDim.x + threadIdx.x) >> 5);
    int lane = threadIdx.x & 31;
    if (node >= N) return;
    const float4* hb = (const float4*)h;
    int beg = __ldg(&offs[node]);
    int end = __ldg(&offs[node + 1]);

    float4 v0 = __ldg(hb + (size_t)node * 32 + lane);
    float4 v1 = make_float4(0.f, 0.f, 0.f, 0.f);
    int i = beg;
    for (; i + 1 < end; i += 2) {
        int s0 = __ldg(&ssrc[i]);
        int s1 = __ldg(&ssrc[i + 1]);
        float4 a = __ldg(hb + (size_t)s0 * 32 + lane);
        float4 b = __ldg(hb + (size_t)s1 * 32 + lane);
        v0.x += a.x; v0.y += a.y; v0.z += a.z; v0.w += a.w;
        v1.x += b.x; v1.y += b.y; v1.z += b.z; v1.w += b.w;
    }
    if (i < end) {
        int s0 = __ldg(&ssrc[i]);
        float4 a = __ldg(hb + (size_t)s0 * 32 + lane);
        v0.x += a.x; v0.y += a.y; v0.z += a.z; v0.w += a.w;
    }
    v0.x += v1.x; v0.y += v1.y; v0.z += v1.z; v0.w += v1.w;
    ((uint2*)agg)[(size_t)node * 32 + lane] = float4_to_half4(v0);
}

// ---------------------------------------------------------------------------
// Gather (fp16 source): layers 2-3; writes fp16 agg.
// ---------------------------------------------------------------------------
__global__ __launch_bounds__(256) void gather_f16_kernel(const __half* __restrict__ h,
                                                         const int* __restrict__ ssrc,
                                                         const int* __restrict__ offs,
                                                         __half* __restrict__ agg,
                                                         int N) {
    int node = (int)(((size_t)blockIdx.x * blockDim.x + threadIdx.x) >> 5);
    int lane = threadIdx.x & 31;
    if (node >= N) return;
    const uint2* hb = (const uint2*)h;
    int beg = __ldg(&offs[node]);
    int end = __ldg(&offs[node + 1]);

    float4 v0 = half4_to_float4(__ldg(hb + (size_t)node * 32 + lane));
    float4 v1 = make_float4(0.f, 0.f, 0.f, 0.f);
    int i = beg;
    for (; i + 1 < end; i += 2) {
        int s0 = __ldg(&ssrc[i]);
        int s1 = __ldg(&ssrc[i + 1]);
        float4 a = half4_to_float4(__ldg(hb + (size_t)s0 * 32 + lane));
        float4 b = half4_to_float4(__ldg(hb + (size_t)s1 * 32 + lane));
        v0.x += a.x; v0.y += a.y; v0.z += a.z; v0.w += a.w;
        v1.x += b.x; v1.y += b.y; v1.z += b.z; v1.w += b.w;
    }
    if (i < end) {
        int s0 = __ldg(&ssrc[i]);
        float4 a = half4_to_float4(__ldg(hb + (size_t)s0 * 32 + lane));
        v0.x += a.x; v0.y += a.y; v0.z += a.z; v0.w += a.w;
    }
    v0.x += v1.x; v0.y += v1.y; v0.z += v1.z; v0.w += v1.w;
    ((uint2*)agg)[(size_t)node * 32 + lane] = float4_to_half4(v0);
}

// ---------------------------------------------------------------------------
// fp16 tensor-core GEMM: C(f16)[M,128] = relu( A(f16) @ Wt^T + b(f32) )
// Wt is [n][k] (k contiguous). Full K=128 resident; single load stage.
// 256 threads = 8 warps (4xM, 2xN); warp tile 32x64 = 2 m x 8 n of m16n8k16.
// smem 68KB -> 3 CTAs/SM; cross-CTA overlap hides the load phase.
// ---------------------------------------------------------------------------
__global__ __launch_bounds__(256) void gemm_f16_kernel(
    const __half* __restrict__ A,
    const __half* __restrict__ Wt,    // [128][128], wt[n][k]
    const float* __restrict__ bias,
    __half* __restrict__ C,
    int M) {
    extern __shared__ __half smem[];
    __half* As = smem;                 // [128][T_PITCH]
    __half* Ws = smem + T_ELEMS;       // [128][T_PITCH]  (n-major, k contiguous)

    const int tid  = threadIdx.x;
    const int lane = tid & 31;
    const int wid  = tid >> 5;
    const int warp_m = (wid & 3) * 32;
    const int warp_n = (wid >> 2) * 64;
    const int g = lane >> 2;           // 0..7
    const int c = lane & 3;            // 0..3
    const int rowBase = blockIdx.x * 128;

    // Load A tile: 128 rows x 128 halves = 2048 x 8-half chunks
#pragma unroll
    for (int i = tid; i < 2048; i += 256) {
        int r  = i >> 4;
        int c8 = (i & 15) * 8;
        int gr = rowBase + r;
        __half* dst = &As[r * T_PITCH + c8];
        if (gr < M) {
            cp_async16(smem_u32(dst), &A[(size_t)gr * HDIM + c8]);
        } else {
            *(uint4*)dst = make_uint4(0, 0, 0, 0);
        }
    }
    // Load Wt tile: 128 n-rows x 128 k
#pragma unroll
    for (int i = tid; i < 2048; i += 256) {
        int r  = i >> 4;
        int c8 = (i & 15) * 8;
        cp_async16(smem_u32(&Ws[r * T_PITCH + c8]), &Wt[(size_t)r * HDIM + c8]);
    }
    cp_commit();
    cp_wait<0>();
    __syncthreads();

    float acc[2][8][4];
#pragma unroll
    for (int mt = 0; mt < 2; mt++)
#pragma unroll
        for (int nt = 0; nt < 8; nt++)
#pragma unroll
            for (int j = 0; j < 4; j++) acc[mt][nt][j] = 0.f;

#pragma unroll
    for (int ks = 0; ks < 8; ks++) {
        const int k0 = ks * 16;
        uint32_t a[2][4];
#pragma unroll
        for (int mt = 0; mt < 2; mt++) {
            int rb = warp_m + mt * 16;
            // m16n8k16 A frag (row-major): pairs at (g,2c),(g+8,2c),(g,2c+8),(g+8,2c+8)
            a[mt][0] = *(const uint32_t*)&As[(rb + g    ) * T_PITCH + k0 + 2 * c    ];
            a[mt][1] = *(const uint32_t*)&As[(rb + 8 + g) * T_PITCH + k0 + 2 * c    ];
            a[mt][2] = *(const uint32_t*)&As[(rb + g    ) * T_PITCH + k0 + 2 * c + 8];
            a[mt][3] = *(const uint32_t*)&As[(rb + 8 + g) * T_PITCH + k0 + 2 * c + 8];
        }
#pragma unroll
        for (int nt = 0; nt < 8; nt++) {
            int n = warp_n + nt * 8 + g;
            // B frag (col-major k16xn8): pairs at (2c,n),(2c+8,n) -> Ws[n][k] contiguous
            uint32_t b0 = *(const uint32_t*)&Ws[n * T_PITCH + k0 + 2 * c    ];
            uint32_t b1 = *(const uint32_t*)&Ws[n * T_PITCH + k0 + 2 * c + 8];
#pragma unroll
            for (int mt = 0; mt < 2; mt++)
                mma_f16(acc[mt][nt], a[mt][0], a[mt][1], a[mt][2], a[mt][3], b0, b1);
        }
    }

    // Epilogue: bias + relu -> fp16
#pragma unroll
    for (int nt = 0; nt < 8; nt++) {
        int col = warp_n + nt * 8 + 2 * c;
        float2 bb = *(const float2*)&bias[col];
#pragma unroll
        for (int mt = 0; mt < 2; mt++) {
            int row0 = rowBase + warp_m + mt * 16 + g;
            int row1 = row0 + 8;
            if (row0 < M) {
                float ox = fmaxf(acc[mt][nt][0] + bb.x, 0.f);
                float oy = fmaxf(acc[mt][nt][1] + bb.y, 0.f);
                ((__half2*)C)[((size_t)row0 * HDIM + col) >> 1] = __floats2half2_rn(ox, oy);
            }
            if (row1 < M) {
                float ox = fmaxf(acc[mt][nt][2] + bb.x, 0.f);
                float oy = fmaxf(acc[mt][nt][3] + bb.y, 0.f);
                ((__half2*)C)[((size_t)row1 * HDIM + col) >> 1] = __floats2half2_rn(ox, oy);
            }
        }
    }
}

// ---------------------------------------------------------------------------
// Final zero + pool (pool reads fp16 h, accumulates fp32 atomics)
// ---------------------------------------------------------------------------
__global__ void zero_kernel(float4* __restrict__ p, size_t n4) {
    size_t i = (size_t)blockIdx.x * blockDim.x + threadIdx.x;
    if (i < n4) p[i] = make_float4(0.f, 0.f, 0.f, 0.f);
}

__global__ void pool_kernel(const __half* __restrict__ h,
                            const int* __restrict__ batch,
                            float* __restrict__ out,
                            int M) {
    int warp = (int)(((size_t)blockIdx.x * blockDim.x + threadIdx.x) >> 5);
    int lane = threadIdx.x & 31;
    if (warp >= M) return;
    int g = __ldg(&batch[warp]);
    float4 v = half4_to_float4(__ldg(((const uint2*)h) + (size_t)warp * 32 + lane));
    atomic_add_f4(((float4*)(out + (size_t)g * HDIM)) + lane, v);
}

// ---------------------------------------------------------------------------
// Launch
// ---------------------------------------------------------------------------
extern "C" void kernel_launch(void* const* d_in, const int* in_sizes, int n_in,
                              void* d_out, int out_size) {
    const float* x     = (const float*)d_in[0];
    const int*   ei    = (const int*)d_in[1];
    const int*   batch = (const int*)d_in[2];
    const float* Wsrc[6] = {(const float*)d_in[3], (const float*)d_in[5],
                            (const float*)d_in[7], (const float*)d_in[9],
                            (const float*)d_in[11], (const float*)d_in[13]};
    const float* b1[3] = {(const float*)d_in[4], (const float*)d_in[8],  (const float*)d_in[12]};
    const float* b2[3] = {(const float*)d_in[6], (const float*)d_in[10], (const float*)d_in[14]};

    const int Nn = in_sizes[0] / HDIM;
    const int Ee = in_sizes[1] / 2;
    const int* src = ei;
    const int* dst = ei + Ee;

    __half *agg, *zbuf, *h0, *h1, *wth;
    int *offs, *cursor, *ssrc, *bsum;
    cudaGetSymbolAddress((void**)&agg,    g_agg);
    cudaGetSymbolAddress((void**)&zbuf,   g_z);
    cudaGetSymbolAddress((void**)&h0,     g_h0h);
    cudaGetSymbolAddress((void**)&h1,     g_h1h);
    cudaGetSymbolAddress((void**)&offs,   g_offs);
    cudaGetSymbolAddress((void**)&cursor, g_cursor);
    cudaGetSymbolAddress((void**)&ssrc,   g_ssrc);
    cudaGetSymbolAddress((void**)&bsum,   g_bsum);
    cudaGetSymbolAddress((void**)&wth,    g_wth);
    __half* hbuf[2] = {h0, h1};

    cudaFuncSetAttribute(gemm_f16_kernel,
                         cudaFuncAttributeMaxDynamicSharedMemorySize, GEMM_SMEM_BYTES);

    // --- Prep weights: fp16 + transpose, one launch ---
    prep_w6_kernel<<<(6 * HDIM * HDIM + 255) / 256, 256>>>(
        wth, Wsrc[0], Wsrc[1], Wsrc[2], Wsrc[3], Wsrc[4], Wsrc[5]);

    // --- Build CSR (dst-sorted src list) ---
    const int nb = (Nn + 1023) / 1024;
    zero_int_kernel<<<(Nn + 255) / 256, 256>>>(cursor, Nn);
    hist_kernel<<<(Ee + 255) / 256, 256>>>(dst, cursor, Ee);
    scan1_kernel<<<nb, 1024>>>(cursor, offs, bsum, Nn);
    scan2_kernel<<<1, NB_MAX>>>(bsum, nb);
    scan3_kernel<<<nb, 1024>>>(offs, cursor, bsum, Nn, nb);
    permute_kernel<<<(Ee + 255) / 256, 256>>>(src, dst, cursor, ssrc, Ee);

    const int gm_blocks   = (Nn + 127) / 128;
    const int ga_blocks   = (Nn + 7) / 8;
    const int pool_blocks = (Nn + 7) / 8;

    const __half* hin_h = nullptr;
    for (int layer = 0; layer < 3; layer++) {
        __half* hout = hbuf[layer & 1];
        const __half* w1 = wth + (size_t)(2 * layer)     * HDIM * HDIM;
        const __half* w2 = wth + (size_t)(2 * layer + 1) * HDIM * HDIM;
        if (layer == 0)
            gather_f32_kernel<<<ga_blocks, 256>>>(x, ssrc, offs, agg, Nn);
        else
            gather_f16_kernel<<<ga_blocks, 256>>>(hin_h, ssrc, offs, agg, Nn);
        gemm_f16_kernel<<<gm_blocks, 256, GEMM_SMEM_BYTES>>>(agg,  w1, b1[layer], zbuf, Nn);
        gemm_f16_kernel<<<gm_blocks, 256, GEMM_SMEM_BYTES>>>(zbuf, w2, b2[layer], hout, Nn);
        hin_h = hout;
    }

    float* out = (float*)d_out;
    const int zo_blocks = (out_size / 4 + 255) / 256;
    zero_kernel<<<zo_blocks, 256>>>((float4*)out, out_size / 4);
    pool_kernel<<<pool_blocks, 256>>>(hin_h, batch, out, Nn);
}